// round 2
// baseline (speedup 1.0000x reference)
#include <cuda_runtime.h>

#define B_    16
#define NNODE 7
#define HID_  256
#define C_    256
#define P_    (96 * 96)     // 9216
#define P4_   (P_ / 4)      // 2304 float4 per channel

// Scratch: per-(b,c) output value (relu already applied). 16 KB.
__device__ float g_v[B_ * C_];

// ───────────────────────── Kernel 1: compute v[b,c] ─────────────────────────
// grid = 16 (one block per batch b), block = 256 (thread t == hidden index,
// then thread t == channel index in phase 2).
__global__ __launch_bounds__(256)
void g2f_compute_kernel(const float* __restrict__ x,    // (B, NNODE, HID)
                        const float* __restrict__ nfh,  // (HID)
                        const float* __restrict__ W)    // (HID, C)
{
    const int b = blockIdx.x;
    const int t = threadIdx.x;
    const int lane = t & 31;
    const int warp = t >> 5;

    __shared__ float wsum[8][NNODE];
    __shared__ float s_hid[NNODE];
    __shared__ float y_sh[HID_];

    const float* xb = x + (size_t)b * NNODE * HID_;
    float xh[NNODE];
#pragma unroll
    for (int n = 0; n < NNODE; n++) xh[n] = xb[n * HID_ + t];
    const float nf = nfh[t];

    // s_hid[n] = sum_h x[b,n,h]*nfh[h]
    float p[NNODE];
#pragma unroll
    for (int n = 0; n < NNODE; n++) p[n] = xh[n] * nf;
#pragma unroll
    for (int off = 16; off > 0; off >>= 1)
#pragma unroll
        for (int n = 0; n < NNODE; n++)
            p[n] += __shfl_down_sync(0xFFFFFFFFu, p[n], off);
    if (lane == 0)
#pragma unroll
        for (int n = 0; n < NNODE; n++) wsum[warp][n] = p[n];
    __syncthreads();
    if (t < NNODE) {
        float s = 0.f;
#pragma unroll
        for (int w = 0; w < 8; w++) s += wsum[w][t];
        s_hid[t] = s;
    }
    __syncthreads();

    // softmax over 7 nodes (redundant per thread)
    float m = s_hid[0];
#pragma unroll
    for (int n = 1; n < NNODE; n++) m = fmaxf(m, s_hid[n]);
    float a[NNODE]; float esum = 0.f;
#pragma unroll
    for (int n = 0; n < NNODE; n++) { a[n] = __expf(s_hid[n] - m); esum += a[n]; }
    const float inv = 1.0f / esum;

    // y[h] = sum_n a[n] * x[b,n,h]
    float y = 0.f;
#pragma unroll
    for (int n = 0; n < NNODE; n++) y = fmaf(a[n] * inv, xh[n], y);
    y_sh[t] = y;
    __syncthreads();

    // v[b,t] = relu( sum_h y[h] * W[h,t] )  — W rows read coalesced across t
    float v = 0.f;
#pragma unroll 8
    for (int h = 0; h < HID_; h++)
        v = fmaf(y_sh[h], W[h * C_ + t], v);
    g_v[b * C_ + t] = fmaxf(v, 0.0f);
}

// ───────────────────────── Kernel 2: broadcast fill ─────────────────────────
// grid = (C_, B_) = 4096 blocks, 256 threads. One broadcast LDG, then 9
// independent STG.128 per thread. No barriers, no reductions.
__global__ __launch_bounds__(256)
void g2f_fill_kernel(float* __restrict__ out)            // (B, C, P)
{
    const int c = blockIdx.x;
    const int b = blockIdx.y;
    const int t = threadIdx.x;

    const float v = __ldg(&g_v[b * C_ + c]);
    const float4 val = make_float4(v, v, v, v);
    float4* o = reinterpret_cast<float4*>(out + (size_t)(b * C_ + c) * P_);
#pragma unroll
    for (int i = 0; i < P4_ / 256; i++)      // 9 iterations
        o[i * 256 + t] = val;
}

extern "C" void kernel_launch(void* const* d_in, const int* in_sizes, int n_in,
                              void* d_out, int out_size)
{
    const float* x   = (const float*)d_in[0];  // (1,16,7,256)
    // d_in[1] res_feature, d_in[2] node_fea_for_res: cancel in softmax — unused
    const float* nfh = (const float*)d_in[3];  // (256,1)
    const float* W   = (const float*)d_in[4];  // (256,256)
    float* out = (float*)d_out;

    g2f_compute_kernel<<<B_, 256>>>(x, nfh, W);
    dim3 grid(C_, B_);
    g2f_fill_kernel<<<grid, 256>>>(out);
}

// round 5
// speedup vs baseline: 1.6057x; 1.6057x over previous
#include <cuda_runtime.h>

#define B_    16
#define NNODE 7
#define HID_  256
#define C_    256
#define P_    (96 * 96)     // 9216
#define P4_   (P_ / 4)      // 2304 float4 per channel
#define CTILE 32            // channels per compute block
#define NCT   (C_ / CTILE)  // 8 c-tiles per batch

// Scratch: per-(b,c) output value (relu applied). 16 KB.
__device__ float g_v[B_ * C_];

// ──────────────── Kernel 1: compute v[b,c]  (grid = 16*8 = 128 blocks) ──────
// blockIdx.x = b * NCT + ctile. 256 threads.
// Phase 1 (thread t == hidden index h): softmax weights + y[b,h], redundant
// across the 8 c-tile blocks of the same b (x slice is 7 KB, L2-deduped).
// Phase 2: warp w owns h-chunk [32w,32w+32), lane owns channel c0+lane.
// Every W load is a coalesced 128B line; 8 warps/block * 128 blocks of MLP.
__global__ __launch_bounds__(256)
void g2f_compute_kernel(const float* __restrict__ x,    // (B, NNODE, HID)
                        const float* __restrict__ nfh,  // (HID)
                        const float* __restrict__ W)    // (HID, C)
{
    const int b  = blockIdx.x / NCT;
    const int c0 = (blockIdx.x % NCT) * CTILE;
    const int t    = threadIdx.x;
    const int lane = t & 31;
    const int warp = t >> 5;

    __shared__ float wsum[8][NNODE];
    __shared__ float s_hid[NNODE];
    __shared__ float y_sh[HID_];
    __shared__ float part[8][CTILE];

    // ---- phase 1: s_hid, softmax, y[b,h] ----
    const float* xb = x + (size_t)b * NNODE * HID_;
    float xh[NNODE];
#pragma unroll
    for (int n = 0; n < NNODE; n++) xh[n] = xb[n * HID_ + t];
    const float nf = nfh[t];

    float p[NNODE];
#pragma unroll
    for (int n = 0; n < NNODE; n++) p[n] = xh[n] * nf;
#pragma unroll
    for (int off = 16; off > 0; off >>= 1)
#pragma unroll
        for (int n = 0; n < NNODE; n++)
            p[n] += __shfl_down_sync(0xFFFFFFFFu, p[n], off);
    if (lane == 0)
#pragma unroll
        for (int n = 0; n < NNODE; n++) wsum[warp][n] = p[n];
    __syncthreads();
    if (t < NNODE) {
        float s = 0.f;
#pragma unroll
        for (int w = 0; w < 8; w++) s += wsum[w][t];
        s_hid[t] = s;
    }
    __syncthreads();

    float m = s_hid[0];
#pragma unroll
    for (int n = 1; n < NNODE; n++) m = fmaxf(m, s_hid[n]);
    float a[NNODE]; float esum = 0.f;
#pragma unroll
    for (int n = 0; n < NNODE; n++) { a[n] = __expf(s_hid[n] - m); esum += a[n]; }
    const float inv = 1.0f / esum;

    float y = 0.f;
#pragma unroll
    for (int n = 0; n < NNODE; n++) y = fmaf(a[n] * inv, xh[n], y);
    y_sh[t] = y;
    __syncthreads();

    // ---- phase 2: v[b, c0+lane] = relu( sum_h y[h] * W[h, c0+lane] ) ----
    // warp 'warp' sums h in [32*warp, 32*warp+32)
    const int h0 = warp * 32;
    float acc = 0.f;
#pragma unroll
    for (int hh = 0; hh < 32; hh++) {
        const int h = h0 + hh;
        acc = fmaf(y_sh[h], W[h * C_ + c0 + lane], acc);
    }
    part[warp][lane] = acc;
    __syncthreads();

    if (warp == 0) {
        float v = 0.f;
#pragma unroll
        for (int w = 0; w < 8; w++) v += part[w][lane];
        g_v[b * C_ + c0 + lane] = fmaxf(v, 0.0f);
    }
}

// ──────────────── Kernel 2: broadcast fill (grid = 4096, 256 thr) ───────────
__global__ __launch_bounds__(256)
void g2f_fill_kernel(float* __restrict__ out)            // (B, C, P)
{
    const int c = blockIdx.x;
    const int b = blockIdx.y;
    const int t = threadIdx.x;

    const float v = __ldg(&g_v[b * C_ + c]);
    const float4 val = make_float4(v, v, v, v);
    float4* o = reinterpret_cast<float4*>(out + (size_t)(b * C_ + c) * P_);
#pragma unroll
    for (int i = 0; i < P4_ / 256; i++)      // 9 iterations, streaming stores
        __stcs(&o[i * 256 + t], val);
}

extern "C" void kernel_launch(void* const* d_in, const int* in_sizes, int n_in,
                              void* d_out, int out_size)
{
    const float* x   = (const float*)d_in[0];  // (1,16,7,256)
    // d_in[1] res_feature, d_in[2] node_fea_for_res: cancel in softmax — unused
    const float* nfh = (const float*)d_in[3];  // (256,1)
    const float* W   = (const float*)d_in[4];  // (256,256)
    float* out = (float*)d_out;

    g2f_compute_kernel<<<B_ * NCT, 256>>>(x, nfh, W);
    dim3 grid(C_, B_);
    g2f_fill_kernel<<<grid, 256>>>(out);
}